// round 13
// baseline (speedup 1.0000x reference)
#include <cuda_runtime.h>

#define MARGIN 0.5f

// Scratch accumulators (no device allocation allowed -> __device__ globals).
// Zero at module load; last block re-zeros each call (graph-replay safe).
__device__ float        g_total;
__device__ unsigned int g_count;
__device__ unsigned int g_arrive;

#define CP_ASYNC16(smem_u32, gptr)                                        \
    asm volatile("cp.async.cg.shared.global [%0], [%1], 16;"              \
                 :: "r"(smem_u32), "l"(gptr) : "memory")
#define CP_COMMIT()  asm volatile("cp.async.commit_group;" ::: "memory")
#define CP_WAIT(n)   asm volatile("cp.async.wait_group %0;" :: "n"(n) : "memory")

// ---------------------------------------------------------------------------
// Fast path: C=64, P=16, N=48, B%4==0.
// Round-13 changes vs the 12.8us plateau (rounds 7-12):
//  1. ZERO-TAIL GRID: 512 blocks x 8 warps, each warp exactly 2 quads ->
//     single resident wave, perfectly balanced (the 1024-block versions lost
//     ~40% to a 140-block second wave).
//  2. DOUBLE-BUFFERED cp.async: stage quad0 + quad1 in separate groups;
//     compute quad0 while quad1's 2KB is in flight -> half the exposed DRAM
//     latency per warp.
//  3. FULLY UNROLLED fixed-16 inner loops: immediate-lane SHFLs, zero
//     branches/BSSY (dynamic-trip loops carried ~2x overhead); masked slots
//     (pvm=-1e30) contribute exact zeros.
// Per-pair register layout (rounds 6-12):
//   nA : even-prob neg slots 0-31; nBm: lanes 0-15 = even slots 32-47,
//   lanes 16-31 = odd slots 0-15; nC: odd slots 16-47;
//   pvm: MARGIN - pos (invalid -> -1e30, relu-self-masking, margin prefolded)
// ---------------------------------------------------------------------------
#define FWARPS 8
#define FTHREADS 256

struct QuadBuf {
    float scores[FWARPS][256];
    int   nidx[FWARPS][192];
    int   pidx[FWARPS][64];
    int   pc4[FWARPS][4];
    int   nc4[FWARPS][4];
};

__device__ __forceinline__ void stage_quad(
    QuadBuf& buf, int warp, int lane, int b0,
    const float* __restrict__ scores,
    const int*   __restrict__ pos_indices,
    const int*   __restrict__ neg_indices,
    const int*   __restrict__ pos_counts,
    const int*   __restrict__ neg_counts)
{
    const float* gs = scores      + (size_t)b0 * 64;   // 1024B, 16B-aligned
    const int*   gn = neg_indices + (size_t)b0 * 48;   // 768B
    const int*   gp = pos_indices + (size_t)b0 * 16;   // 256B

    unsigned ds = (unsigned)__cvta_generic_to_shared(&buf.scores[warp][0]);
    unsigned dn = (unsigned)__cvta_generic_to_shared(&buf.nidx[warp][0]);
    unsigned dp = (unsigned)__cvta_generic_to_shared(&buf.pidx[warp][0]);

    CP_ASYNC16(ds + lane * 16,        gs + lane * 4);
    CP_ASYNC16(ds + (lane + 32) * 16, gs + (lane + 32) * 4);
    CP_ASYNC16(dn + lane * 16,        gn + lane * 4);
    if (lane < 16) {
        CP_ASYNC16(dn + (lane + 32) * 16, gn + (lane + 32) * 4);
        CP_ASYNC16(dp + lane * 16,        gp + lane * 4);
    } else if (lane == 16) {
        unsigned dc = (unsigned)__cvta_generic_to_shared(&buf.pc4[warp][0]);
        CP_ASYNC16(dc, pos_counts + b0);
    } else if (lane == 17) {
        unsigned dc = (unsigned)__cvta_generic_to_shared(&buf.nc4[warp][0]);
        CP_ASYNC16(dc, neg_counts + b0);
    }
}

__device__ __forceinline__ void compute_quad(
    const QuadBuf& buf, int warp, int lane,
    float& acc0, float& acc1, float& acc2, float& acc3, unsigned& cnt)
{
    const bool lo16 = (lane < 16);
    const int  slot = lane & 15;

    const int pc0 = buf.pc4[warp][0], pc1 = buf.pc4[warp][1];
    const int pc2 = buf.pc4[warp][2], pc3 = buf.pc4[warp][3];
    const int nc0 = buf.nc4[warp][0], nc1 = buf.nc4[warp][1];
    const int nc2 = buf.nc4[warp][2], nc3 = buf.nc4[warp][3];

    const int*   nn = buf.nidx[warp];
    const int*   pp = buf.pidx[warp];
    const float* sw = buf.scores[warp];

    const int jA0 = nn[lane];
    const int jA1 = nn[lane + 32];
    const int jA2 = nn[lane + 64];
    const int jB0 = nn[lane + 96];
    const int jB1 = nn[lane + 128];
    const int jB2 = nn[lane + 160];
    const int jPA = pp[lane];
    const int jPB = pp[lane + 32];

    const int offA = lo16 ? 0 : 64;      // mixed row, pair A
    const int offB = lo16 ? 128 : 192;   // mixed row, pair B
    const float gA0 = sw[jA0];
    const float gA1 = sw[offA + jA1];
    const float gA2 = sw[64 + jA2];
    const float gPA = sw[offA + jPA];
    const float gB0 = sw[128 + jB0];
    const float gB1 = sw[offB + jB1];
    const float gB2 = sw[192 + jB2];
    const float gPB = sw[offB + jPB];

    // ---- pair A masks ----
    const float nA_A  = (lane < nc0) ? gA0 : -1e30f;
    const bool  bvA   = lo16 ? (lane + 32 < nc0) : (lane - 16 < nc1);
    const float nBmA  = bvA ? gA1 : -1e30f;
    const float nB0_A = lo16 ? nBmA : -1e30f;
    const float nB1_A = lo16 ? -1e30f : nBmA;
    const float nC_A  = (lane + 16 < nc1) ? gA2 : -1e30f;
    const int   pcOwnA = lo16 ? pc0 : pc1;
    const float pvmA   = (slot < pcOwnA) ? (MARGIN - gPA) : -1e30f;

    // ---- pair B masks ----
    const float nA_B  = (lane < nc2) ? gB0 : -1e30f;
    const bool  bvB   = lo16 ? (lane + 32 < nc2) : (lane - 16 < nc3);
    const float nBmB  = bvB ? gB1 : -1e30f;
    const float nB0_B = lo16 ? nBmB : -1e30f;
    const float nB1_B = lo16 ? -1e30f : nBmB;
    const float nC_B  = (lane + 16 < nc3) ? gB2 : -1e30f;
    const int   pcOwnB = lo16 ? pc2 : pc3;
    const float pvmB   = (slot < pcOwnB) ? (MARGIN - gPB) : -1e30f;

    cnt += (unsigned)(pc0 * nc0) + (unsigned)(pc1 * nc1)
         + (unsigned)(pc2 * nc2) + (unsigned)(pc3 * nc3);

    // ---- fully unrolled: 4 problems x 16 immediate-lane SHFLs each ----
    #pragma unroll
    for (int p = 0; p < 16; p++) {
        const float a = __shfl_sync(0xffffffffu, pvmA, p);
        float t0 = fmaxf(a + nA_A,  0.0f);
        float t1 = fmaxf(a + nB0_A, 0.0f);
        if ((p & 3) == 0) acc0 += t0 + t1;
        else if ((p & 3) == 1) acc1 += t0 + t1;
        else if ((p & 3) == 2) acc2 += t0 + t1;
        else acc3 += t0 + t1;
    }
    #pragma unroll
    for (int p = 0; p < 16; p++) {
        const float a = __shfl_sync(0xffffffffu, pvmA, 16 + p);
        float t0 = fmaxf(a + nB1_A, 0.0f);
        float t1 = fmaxf(a + nC_A,  0.0f);
        if ((p & 3) == 0) acc0 += t0 + t1;
        else if ((p & 3) == 1) acc1 += t0 + t1;
        else if ((p & 3) == 2) acc2 += t0 + t1;
        else acc3 += t0 + t1;
    }
    #pragma unroll
    for (int p = 0; p < 16; p++) {
        const float a = __shfl_sync(0xffffffffu, pvmB, p);
        float t0 = fmaxf(a + nA_B,  0.0f);
        float t1 = fmaxf(a + nB0_B, 0.0f);
        if ((p & 3) == 0) acc0 += t0 + t1;
        else if ((p & 3) == 1) acc1 += t0 + t1;
        else if ((p & 3) == 2) acc2 += t0 + t1;
        else acc3 += t0 + t1;
    }
    #pragma unroll
    for (int p = 0; p < 16; p++) {
        const float a = __shfl_sync(0xffffffffu, pvmB, 16 + p);
        float t0 = fmaxf(a + nB1_B, 0.0f);
        float t1 = fmaxf(a + nC_B,  0.0f);
        if ((p & 3) == 0) acc0 += t0 + t1;
        else if ((p & 3) == 1) acc1 += t0 + t1;
        else if ((p & 3) == 2) acc2 += t0 + t1;
        else acc3 += t0 + t1;
    }
}

__global__ void __launch_bounds__(FTHREADS)
mpcl_fast_kernel(const float* __restrict__ scores,
                 const int*   __restrict__ pos_indices,
                 const int*   __restrict__ neg_indices,
                 const int*   __restrict__ pos_counts,
                 const int*   __restrict__ neg_counts,
                 float*       __restrict__ out,
                 int nQuads)
{
    __shared__ QuadBuf  s_buf[2];
    __shared__ float    s_tot[FWARPS];
    __shared__ unsigned s_cnt[FWARPS];

    const int tid  = threadIdx.x;
    const int warp = tid >> 5;
    const int lane = tid & 31;

    const int stride = gridDim.x * FWARPS;
    const int q0 = blockIdx.x * FWARPS + warp;
    const int q1 = q0 + stride;

    float acc0 = 0.0f, acc1 = 0.0f, acc2 = 0.0f, acc3 = 0.0f;
    unsigned cnt = 0u;

    const bool has0 = (q0 < nQuads);
    const bool has1 = (q1 < nQuads);

    // ---- double-buffered staging: quad1's DRAM trip hides behind quad0 ----
    if (has0) stage_quad(s_buf[0], warp, lane, q0 * 4,
                         scores, pos_indices, neg_indices,
                         pos_counts, neg_counts);
    CP_COMMIT();
    if (has1) stage_quad(s_buf[1], warp, lane, q1 * 4,
                         scores, pos_indices, neg_indices,
                         pos_counts, neg_counts);
    CP_COMMIT();

    if (has0) {
        CP_WAIT(1);          // quad0 ready; quad1 still in flight
        __syncwarp();
        compute_quad(s_buf[0], warp, lane, acc0, acc1, acc2, acc3, cnt);
    }
    if (has1) {
        CP_WAIT(0);          // quad1 ready
        __syncwarp();
        compute_quad(s_buf[1], warp, lane, acc0, acc1, acc2, acc3, cnt);
    }

    float accs = (acc0 + acc1) + (acc2 + acc3);
    #pragma unroll
    for (int o = 16; o > 0; o >>= 1)
        accs += __shfl_xor_sync(0xffffffffu, accs, o);

    if (lane == 0) { s_tot[warp] = accs; s_cnt[warp] = cnt; }
    __syncthreads();

    if (tid == 0) {
        float    t = 0.0f;
        unsigned c = 0u;
        #pragma unroll
        for (int i = 0; i < FWARPS; i++) { t += s_tot[i]; c += s_cnt[i]; }
        // Fence-free finalize (no CCTL.IVALL): release REDs + acq_rel ticket.
        asm volatile("red.add.release.gpu.f32 [%0], %1;"
                     :: "l"(&g_total), "f"(t) : "memory");
        asm volatile("red.add.release.gpu.u32 [%0], %1;"
                     :: "l"(&g_count), "r"(c) : "memory");
        unsigned ticket;
        asm volatile("atom.add.acq_rel.gpu.u32 %0, [%1], %2;"
                     : "=r"(ticket) : "l"(&g_arrive), "r"(1u) : "memory");
        if (ticket == (unsigned)gridDim.x - 1u) {
            float tv; unsigned cv;
            asm volatile("ld.acquire.gpu.f32 %0, [%1];"
                         : "=f"(tv) : "l"(&g_total) : "memory");
            asm volatile("ld.acquire.gpu.u32 %0, [%1];"
                         : "=r"(cv) : "l"(&g_count) : "memory");
            out[0] = (cv > 0u) ? (tv / (float)cv) : 0.0f;
            g_total = 0.0f; g_count = 0u; g_arrive = 0u;
        }
    }
}

// ---------------------------------------------------------------------------
// Generic fallback (round-5 proven kernel), used only if shape differs.
// ---------------------------------------------------------------------------
#define GWARPS 16
#define GTHREADS (GWARPS * 32)

__global__ void __launch_bounds__(GTHREADS, 4)
mpcl_generic_kernel(const float* __restrict__ scores,
                    const int*   __restrict__ pos_indices,
                    const int*   __restrict__ neg_indices,
                    const int*   __restrict__ pos_counts,
                    const int*   __restrict__ neg_counts,
                    float*       __restrict__ out,
                    int B, int C, int P, int N, int nPairs)
{
    __shared__ float    s_tot[GWARPS];
    __shared__ unsigned s_cnt[GWARPS];

    const int warp    = threadIdx.x >> 5;
    const int lane    = threadIdx.x & 31;
    const int gwarp   = blockIdx.x * GWARPS + warp;
    const int wstride = gridDim.x * GWARPS;
    const bool loHalf = (lane < 16);

    float    acc0 = 0.0f, acc1 = 0.0f;
    unsigned cnt  = 0u;

    for (int q = gwarp; q < nPairs; q += wstride) {
        const int  b0   = q * 2;
        const int  b1   = b0 + 1;
        const bool has1 = (b1 < B);

        const int pc0 = min(pos_counts[b0], 16);
        const int nc0 = neg_counts[b0];
        const int pc1 = has1 ? min(pos_counts[b1], 16) : 0;
        const int nc1 = has1 ? neg_counts[b1]          : 0;

        const float* s0  = scores + (size_t)b0 * (size_t)C;
        const float* s1  = scores + (size_t)b1 * (size_t)C;
        const int*   n0p = neg_indices + (size_t)b0 * (size_t)N;
        const int*   n1p = neg_indices + (size_t)b1 * (size_t)N;

        const int    slot  = lane & 15;
        const bool   myOk  = loHalf || has1;
        const int*   pbase = loHalf ? (pos_indices + (size_t)b0 * (size_t)P)
                                    : (pos_indices + (size_t)b1 * (size_t)P);
        const int    jp    = (myOk && slot < P) ? pbase[slot] : 0;
        const float* sbase = loHalf ? s0 : s1;
        float pv = myOk ? sbase[jp] : 1e30f;
        const int pcOwn = loHalf ? pc0 : pc1;
        pv = (slot < pcOwn) ? pv : 1e30f;

        const int j00 = (lane      < N) ? n0p[lane]      : 0;
        const int j01 = (lane + 32 < N) ? n0p[lane + 32] : 0;
        float n00 = (lane      < nc0) ? s0[j00] : -1e30f;
        float n01 = (lane + 32 < nc0) ? s0[j01] : -1e30f;

        float n10 = -1e30f, n11 = -1e30f;
        if (has1) {
            const int j10 = (lane      < N) ? n1p[lane]      : 0;
            const int j11 = (lane + 32 < N) ? n1p[lane + 32] : 0;
            n10 = (lane      < nc1) ? s1[j10] : -1e30f;
            n11 = (lane + 32 < nc1) ? s1[j11] : -1e30f;
        }

        cnt += (unsigned)(pc0 * nc0) + (unsigned)(pc1 * nc1);

        const int it0 = (nc0 > 0) ? pc0 : 0;
        for (int pg = 0; pg < it0; pg += 4) {
            const float x0 = __shfl_sync(0xffffffffu, pv, pg + 0);
            const float x1 = __shfl_sync(0xffffffffu, pv, pg + 1);
            const float x2 = __shfl_sync(0xffffffffu, pv, pg + 2);
            const float x3 = __shfl_sync(0xffffffffu, pv, pg + 3);
            const float a0 = MARGIN - x0, a1 = MARGIN - x1;
            const float a2 = MARGIN - x2, a3 = MARGIN - x3;
            acc0 += fmaxf(a0 + n00, 0.0f) + fmaxf(a1 + n00, 0.0f)
                  + fmaxf(a2 + n00, 0.0f) + fmaxf(a3 + n00, 0.0f);
            acc1 += fmaxf(a0 + n01, 0.0f) + fmaxf(a1 + n01, 0.0f)
                  + fmaxf(a2 + n01, 0.0f) + fmaxf(a3 + n01, 0.0f);
        }
        const int it1 = (nc1 > 0) ? pc1 : 0;
        for (int pg = 0; pg < it1; pg += 4) {
            const float x0 = __shfl_sync(0xffffffffu, pv, 16 + pg + 0);
            const float x1 = __shfl_sync(0xffffffffu, pv, 16 + pg + 1);
            const float x2 = __shfl_sync(0xffffffffu, pv, 16 + pg + 2);
            const float x3 = __shfl_sync(0xffffffffu, pv, 16 + pg + 3);
            const float a0 = MARGIN - x0, a1 = MARGIN - x1;
            const float a2 = MARGIN - x2, a3 = MARGIN - x3;
            acc0 += fmaxf(a0 + n10, 0.0f) + fmaxf(a1 + n10, 0.0f)
                  + fmaxf(a2 + n10, 0.0f) + fmaxf(a3 + n10, 0.0f);
            acc1 += fmaxf(a0 + n11, 0.0f) + fmaxf(a1 + n11, 0.0f)
                  + fmaxf(a2 + n11, 0.0f) + fmaxf(a3 + n11, 0.0f);
        }
    }

    float accs = acc0 + acc1;
    #pragma unroll
    for (int o = 16; o > 0; o >>= 1)
        accs += __shfl_xor_sync(0xffffffffu, accs, o);

    if (lane == 0) { s_tot[warp] = accs; s_cnt[warp] = cnt; }
    __syncthreads();

    if (threadIdx.x == 0) {
        float    t = 0.0f;
        unsigned c = 0u;
        #pragma unroll
        for (int i = 0; i < GWARPS; i++) { t += s_tot[i]; c += s_cnt[i]; }
        asm volatile("red.add.release.gpu.f32 [%0], %1;"
                     :: "l"(&g_total), "f"(t) : "memory");
        asm volatile("red.add.release.gpu.u32 [%0], %1;"
                     :: "l"(&g_count), "r"(c) : "memory");
        unsigned ticket;
        asm volatile("atom.add.acq_rel.gpu.u32 %0, [%1], %2;"
                     : "=r"(ticket) : "l"(&g_arrive), "r"(1u) : "memory");
        if (ticket == (unsigned)gridDim.x - 1u) {
            float tv; unsigned cv;
            asm volatile("ld.acquire.gpu.f32 %0, [%1];"
                         : "=f"(tv) : "l"(&g_total) : "memory");
            asm volatile("ld.acquire.gpu.u32 %0, [%1];"
                         : "=r"(cv) : "l"(&g_count) : "memory");
            out[0] = (cv > 0u) ? (tv / (float)cv) : 0.0f;
            g_total = 0.0f; g_count = 0u; g_arrive = 0u;
        }
    }
}

extern "C" void kernel_launch(void* const* d_in, const int* in_sizes, int n_in,
                              void* d_out, int out_size)
{
    const float* scores      = (const float*)d_in[0];
    const int*   pos_indices = (const int*)  d_in[1];
    const int*   neg_indices = (const int*)  d_in[2];
    const int*   pos_counts  = (const int*)  d_in[3];
    const int*   neg_counts  = (const int*)  d_in[4];
    float*       out         = (float*)d_out;

    const int B = in_sizes[3];
    const int C = in_sizes[0] / B;
    const int P = in_sizes[1] / B;
    const int N = in_sizes[2] / B;

    if (C == 64 && P == 16 && N == 48 && (B % 4) == 0) {
        const int nQuads = B / 4;
        // 2 quads per warp -> single fully-resident wave, zero tail
        const int blocks = (nQuads + 2 * FWARPS - 1) / (2 * FWARPS);
        mpcl_fast_kernel<<<blocks, FTHREADS>>>(
            scores, pos_indices, neg_indices, pos_counts, neg_counts, out,
            nQuads);
    } else {
        const int nPairs = (B + 1) / 2;
        int blocks = (nPairs + GWARPS * 2 - 1) / (GWARPS * 2);
        if (blocks > 592) blocks = 592;
        if (blocks < 1)   blocks = 1;
        mpcl_generic_kernel<<<blocks, GTHREADS>>>(
            scores, pos_indices, neg_indices, pos_counts, neg_counts, out,
            B, C, P, N, nPairs);
    }
}

// round 14
// speedup vs baseline: 1.1450x; 1.1450x over previous
#include <cuda_runtime.h>

#define MARGIN 0.5f

// Scratch accumulators (no device allocation allowed -> __device__ globals).
// Zero at module load; last block re-zeros each call (graph-replay safe).
__device__ float        g_total;
__device__ unsigned int g_count;
__device__ unsigned int g_arrive;

// ---------------------------------------------------------------------------
// Fast path: C=64, P=16, N=48, B%4==0. One warp = one QUAD of problems.
// Body = round-9 proven kernel (best family: 12.8-13.0us, rel_err 0).
// ROUND-14 single-variable change: 4-warp (128-thread) blocks, 2048 blocks.
// Same 8192 warps / same instruction stream; finer block granularity cuts
// per-SM block-quantization (6.92/SM +-14% -> 13.8/SM +-7%), packs the
// scheduler tighter, and couples reduce-stragglers to 4 warps instead of 8.
// Per-pair register layout (rounds 6-13):
//   nA : even-prob neg slots 0-31; nBm: lanes 0-15 = even slots 32-47,
//   lanes 16-31 = odd slots 0-15; nC: odd slots 16-47;
//   pvm: MARGIN - pos (invalid -> -1e30, relu-self-masking, margin prefolded)
// ---------------------------------------------------------------------------
#define FWARPS 4
#define FTHREADS (FWARPS * 32)

__global__ void __launch_bounds__(FTHREADS, 12)
mpcl_fast_kernel(const float* __restrict__ scores,
                 const int*   __restrict__ pos_indices,
                 const int*   __restrict__ neg_indices,
                 const int*   __restrict__ pos_counts,
                 const int*   __restrict__ neg_counts,
                 float*       __restrict__ out,
                 int nQuads)
{
    __shared__ float    s_tot[FWARPS];
    __shared__ unsigned s_cnt[FWARPS];

    const int warp = threadIdx.x >> 5;
    const int lane = threadIdx.x & 31;
    const int q    = blockIdx.x * FWARPS + warp;

    float acc0 = 0.0f, acc1 = 0.0f, acc2 = 0.0f, acc3 = 0.0f;
    unsigned cnt = 0u;

    if (q < nQuads) {
        const int b0    = q * 4;
        const bool lo16 = (lane < 16);
        const int  slot = lane & 15;

        // ---- hoisted loads: counts + indices, all independent ----
        const int2 pcA = *reinterpret_cast<const int2*>(pos_counts + b0);
        const int2 pcB = *reinterpret_cast<const int2*>(pos_counts + b0 + 2);
        const int2 ncA = *reinterpret_cast<const int2*>(neg_counts + b0);
        const int2 ncB = *reinterpret_cast<const int2*>(neg_counts + b0 + 2);

        const int* nn = neg_indices + (size_t)b0 * 48;  // 192 contiguous ints
        const int* pp = pos_indices + (size_t)b0 * 16;  // 64 contiguous ints
        const int jA0 = nn[lane];
        const int jA1 = nn[lane + 32];
        const int jA2 = nn[lane + 64];
        const int jB0 = nn[lane + 96];
        const int jB1 = nn[lane + 128];
        const int jB2 = nn[lane + 160];
        const int jPA = pp[lane];
        const int jPB = pp[lane + 32];

        // ---- hoisted gathers: 8 back-to-back (one amortized latency) ----
        const float* r0 = scores + (size_t)b0 * 64;
        const float* r1 = r0 + 64;
        const float* r2 = r0 + 128;
        const float* r3 = r0 + 192;
        const float* rA = lo16 ? r0 : r1;
        const float* rB = lo16 ? r2 : r3;
        const float gA0 = r0[jA0];
        const float gA1 = rA[jA1];
        const float gA2 = r1[jA2];
        const float gPA = rA[jPA];
        const float gB0 = r2[jB0];
        const float gB1 = rB[jB1];
        const float gB2 = r3[jB2];
        const float gPB = rB[jPB];

        // ---- pair A masks (problems b0, b0+1) ----
        const int pc0 = pcA.x, pc1 = pcA.y;
        const int nc0 = ncA.x, nc1 = ncA.y;
        const float nA_A  = (lane < nc0) ? gA0 : -1e30f;
        const bool  bvA   = lo16 ? (lane + 32 < nc0) : (lane - 16 < nc1);
        const float nBmA  = bvA ? gA1 : -1e30f;
        const float nB0_A = lo16 ? nBmA : -1e30f;
        const float nB1_A = lo16 ? -1e30f : nBmA;
        const float nC_A  = (lane + 16 < nc1) ? gA2 : -1e30f;
        const int   pcOwnA = lo16 ? pc0 : pc1;
        const float pvmA   = (slot < pcOwnA) ? (MARGIN - gPA) : -1e30f;

        // ---- pair B masks (problems b0+2, b0+3) ----
        const int pc2 = pcB.x, pc3 = pcB.y;
        const int nc2 = ncB.x, nc3 = ncB.y;
        const float nA_B  = (lane < nc2) ? gB0 : -1e30f;
        const bool  bvB   = lo16 ? (lane + 32 < nc2) : (lane - 16 < nc3);
        const float nBmB  = bvB ? gB1 : -1e30f;
        const float nB0_B = lo16 ? nBmB : -1e30f;
        const float nB1_B = lo16 ? -1e30f : nBmB;
        const float nC_B  = (lane + 16 < nc3) ? gB2 : -1e30f;
        const int   pcOwnB = lo16 ? pc2 : pc3;
        const float pvmB   = (slot < pcOwnB) ? (MARGIN - gPB) : -1e30f;

        cnt = (unsigned)(pc0 * nc0) + (unsigned)(pc1 * nc1)
            + (unsigned)(pc2 * nc2) + (unsigned)(pc3 * nc3);

        // ---- problem b0 (no nc guard: masked negs give exact 0) ----
        for (int pg = 0; pg < pc0; pg += 4) {
            const float a0 = __shfl_sync(0xffffffffu, pvmA, pg + 0);
            const float a1 = __shfl_sync(0xffffffffu, pvmA, pg + 1);
            const float a2 = __shfl_sync(0xffffffffu, pvmA, pg + 2);
            const float a3 = __shfl_sync(0xffffffffu, pvmA, pg + 3);
            acc0 += fmaxf(a0 + nA_A, 0.0f) + fmaxf(a0 + nB0_A, 0.0f);
            acc1 += fmaxf(a1 + nA_A, 0.0f) + fmaxf(a1 + nB0_A, 0.0f);
            acc2 += fmaxf(a2 + nA_A, 0.0f) + fmaxf(a2 + nB0_A, 0.0f);
            acc3 += fmaxf(a3 + nA_A, 0.0f) + fmaxf(a3 + nB0_A, 0.0f);
        }
        // ---- problem b0+1 ----
        for (int pg = 0; pg < pc1; pg += 4) {
            const float a0 = __shfl_sync(0xffffffffu, pvmA, 16 + pg + 0);
            const float a1 = __shfl_sync(0xffffffffu, pvmA, 16 + pg + 1);
            const float a2 = __shfl_sync(0xffffffffu, pvmA, 16 + pg + 2);
            const float a3 = __shfl_sync(0xffffffffu, pvmA, 16 + pg + 3);
            acc0 += fmaxf(a0 + nB1_A, 0.0f) + fmaxf(a0 + nC_A, 0.0f);
            acc1 += fmaxf(a1 + nB1_A, 0.0f) + fmaxf(a1 + nC_A, 0.0f);
            acc2 += fmaxf(a2 + nB1_A, 0.0f) + fmaxf(a2 + nC_A, 0.0f);
            acc3 += fmaxf(a3 + nB1_A, 0.0f) + fmaxf(a3 + nC_A, 0.0f);
        }
        // ---- problem b0+2 ----
        for (int pg = 0; pg < pc2; pg += 4) {
            const float a0 = __shfl_sync(0xffffffffu, pvmB, pg + 0);
            const float a1 = __shfl_sync(0xffffffffu, pvmB, pg + 1);
            const float a2 = __shfl_sync(0xffffffffu, pvmB, pg + 2);
            const float a3 = __shfl_sync(0xffffffffu, pvmB, pg + 3);
            acc0 += fmaxf(a0 + nA_B, 0.0f) + fmaxf(a0 + nB0_B, 0.0f);
            acc1 += fmaxf(a1 + nA_B, 0.0f) + fmaxf(a1 + nB0_B, 0.0f);
            acc2 += fmaxf(a2 + nA_B, 0.0f) + fmaxf(a2 + nB0_B, 0.0f);
            acc3 += fmaxf(a3 + nA_B, 0.0f) + fmaxf(a3 + nB0_B, 0.0f);
        }
        // ---- problem b0+3 ----
        for (int pg = 0; pg < pc3; pg += 4) {
            const float a0 = __shfl_sync(0xffffffffu, pvmB, 16 + pg + 0);
            const float a1 = __shfl_sync(0xffffffffu, pvmB, 16 + pg + 1);
            const float a2 = __shfl_sync(0xffffffffu, pvmB, 16 + pg + 2);
            const float a3 = __shfl_sync(0xffffffffu, pvmB, 16 + pg + 3);
            acc0 += fmaxf(a0 + nB1_B, 0.0f) + fmaxf(a0 + nC_B, 0.0f);
            acc1 += fmaxf(a1 + nB1_B, 0.0f) + fmaxf(a1 + nC_B, 0.0f);
            acc2 += fmaxf(a2 + nB1_B, 0.0f) + fmaxf(a2 + nC_B, 0.0f);
            acc3 += fmaxf(a3 + nB1_B, 0.0f) + fmaxf(a3 + nC_B, 0.0f);
        }
    }

    float accs = (acc0 + acc1) + (acc2 + acc3);
    #pragma unroll
    for (int o = 16; o > 0; o >>= 1)
        accs += __shfl_xor_sync(0xffffffffu, accs, o);

    if (lane == 0) { s_tot[warp] = accs; s_cnt[warp] = cnt; }
    __syncthreads();

    if (threadIdx.x == 0) {
        float    t = 0.0f;
        unsigned c = 0u;
        #pragma unroll
        for (int i = 0; i < FWARPS; i++) { t += s_tot[i]; c += s_cnt[i]; }
        // Fence-free finalize (no CCTL.IVALL): release REDs + acq_rel ticket.
        asm volatile("red.add.release.gpu.f32 [%0], %1;"
                     :: "l"(&g_total), "f"(t) : "memory");
        asm volatile("red.add.release.gpu.u32 [%0], %1;"
                     :: "l"(&g_count), "r"(c) : "memory");
        unsigned ticket;
        asm volatile("atom.add.acq_rel.gpu.u32 %0, [%1], %2;"
                     : "=r"(ticket) : "l"(&g_arrive), "r"(1u) : "memory");
        if (ticket == (unsigned)gridDim.x - 1u) {
            float tv; unsigned cv;
            asm volatile("ld.acquire.gpu.f32 %0, [%1];"
                         : "=f"(tv) : "l"(&g_total) : "memory");
            asm volatile("ld.acquire.gpu.u32 %0, [%1];"
                         : "=r"(cv) : "l"(&g_count) : "memory");
            out[0] = (cv > 0u) ? (tv / (float)cv) : 0.0f;
            g_total = 0.0f; g_count = 0u; g_arrive = 0u;
        }
    }
}

// ---------------------------------------------------------------------------
// Generic fallback (round-5 proven kernel), used only if shape differs.
// ---------------------------------------------------------------------------
#define GWARPS 16
#define GTHREADS (GWARPS * 32)

__global__ void __launch_bounds__(GTHREADS, 4)
mpcl_generic_kernel(const float* __restrict__ scores,
                    const int*   __restrict__ pos_indices,
                    const int*   __restrict__ neg_indices,
                    const int*   __restrict__ pos_counts,
                    const int*   __restrict__ neg_counts,
                    float*       __restrict__ out,
                    int B, int C, int P, int N, int nPairs)
{
    __shared__ float    s_tot[GWARPS];
    __shared__ unsigned s_cnt[GWARPS];

    const int warp    = threadIdx.x >> 5;
    const int lane    = threadIdx.x & 31;
    const int gwarp   = blockIdx.x * GWARPS + warp;
    const int wstride = gridDim.x * GWARPS;
    const bool loHalf = (lane < 16);

    float    acc0 = 0.0f, acc1 = 0.0f;
    unsigned cnt  = 0u;

    for (int q = gwarp; q < nPairs; q += wstride) {
        const int  b0   = q * 2;
        const int  b1   = b0 + 1;
        const bool has1 = (b1 < B);

        const int pc0 = min(pos_counts[b0], 16);
        const int nc0 = neg_counts[b0];
        const int pc1 = has1 ? min(pos_counts[b1], 16) : 0;
        const int nc1 = has1 ? neg_counts[b1]          : 0;

        const float* s0  = scores + (size_t)b0 * (size_t)C;
        const float* s1  = scores + (size_t)b1 * (size_t)C;
        const int*   n0p = neg_indices + (size_t)b0 * (size_t)N;
        const int*   n1p = neg_indices + (size_t)b1 * (size_t)N;

        const int    slot  = lane & 15;
        const bool   myOk  = loHalf || has1;
        const int*   pbase = loHalf ? (pos_indices + (size_t)b0 * (size_t)P)
                                    : (pos_indices + (size_t)b1 * (size_t)P);
        const int    jp    = (myOk && slot < P) ? pbase[slot] : 0;
        const float* sbase = loHalf ? s0 : s1;
        float pv = myOk ? sbase[jp] : 1e30f;
        const int pcOwn = loHalf ? pc0 : pc1;
        pv = (slot < pcOwn) ? pv : 1e30f;

        const int j00 = (lane      < N) ? n0p[lane]      : 0;
        const int j01 = (lane + 32 < N) ? n0p[lane + 32] : 0;
        float n00 = (lane      < nc0) ? s0[j00] : -1e30f;
        float n01 = (lane + 32 < nc0) ? s0[j01] : -1e30f;

        float n10 = -1e30f, n11 = -1e30f;
        if (has1) {
            const int j10 = (lane      < N) ? n1p[lane]      : 0;
            const int j11 = (lane + 32 < N) ? n1p[lane + 32] : 0;
            n10 = (lane      < nc1) ? s1[j10] : -1e30f;
            n11 = (lane + 32 < nc1) ? s1[j11] : -1e30f;
        }

        cnt += (unsigned)(pc0 * nc0) + (unsigned)(pc1 * nc1);

        const int it0 = (nc0 > 0) ? pc0 : 0;
        for (int pg = 0; pg < it0; pg += 4) {
            const float x0 = __shfl_sync(0xffffffffu, pv, pg + 0);
            const float x1 = __shfl_sync(0xffffffffu, pv, pg + 1);
            const float x2 = __shfl_sync(0xffffffffu, pv, pg + 2);
            const float x3 = __shfl_sync(0xffffffffu, pv, pg + 3);
            const float a0 = MARGIN - x0, a1 = MARGIN - x1;
            const float a2 = MARGIN - x2, a3 = MARGIN - x3;
            acc0 += fmaxf(a0 + n00, 0.0f) + fmaxf(a1 + n00, 0.0f)
                  + fmaxf(a2 + n00, 0.0f) + fmaxf(a3 + n00, 0.0f);
            acc1 += fmaxf(a0 + n01, 0.0f) + fmaxf(a1 + n01, 0.0f)
                  + fmaxf(a2 + n01, 0.0f) + fmaxf(a3 + n01, 0.0f);
        }
        const int it1 = (nc1 > 0) ? pc1 : 0;
        for (int pg = 0; pg < it1; pg += 4) {
            const float x0 = __shfl_sync(0xffffffffu, pv, 16 + pg + 0);
            const float x1 = __shfl_sync(0xffffffffu, pv, 16 + pg + 1);
            const float x2 = __shfl_sync(0xffffffffu, pv, 16 + pg + 2);
            const float x3 = __shfl_sync(0xffffffffu, pv, 16 + pg + 3);
            const float a0 = MARGIN - x0, a1 = MARGIN - x1;
            const float a2 = MARGIN - x2, a3 = MARGIN - x3;
            acc0 += fmaxf(a0 + n10, 0.0f) + fmaxf(a1 + n10, 0.0f)
                  + fmaxf(a2 + n10, 0.0f) + fmaxf(a3 + n10, 0.0f);
            acc1 += fmaxf(a0 + n11, 0.0f) + fmaxf(a1 + n11, 0.0f)
                  + fmaxf(a2 + n11, 0.0f) + fmaxf(a3 + n11, 0.0f);
        }
    }

    float accs = acc0 + acc1;
    #pragma unroll
    for (int o = 16; o > 0; o >>= 1)
        accs += __shfl_xor_sync(0xffffffffu, accs, o);

    if (lane == 0) { s_tot[warp] = accs; s_cnt[warp] = cnt; }
    __syncthreads();

    if (threadIdx.x == 0) {
        float    t = 0.0f;
        unsigned c = 0u;
        #pragma unroll
        for (int i = 0; i < GWARPS; i++) { t += s_tot[i]; c += s_cnt[i]; }
        asm volatile("red.add.release.gpu.f32 [%0], %1;"
                     :: "l"(&g_total), "f"(t) : "memory");
        asm volatile("red.add.release.gpu.u32 [%0], %1;"
                     :: "l"(&g_count), "r"(c) : "memory");
        unsigned ticket;
        asm volatile("atom.add.acq_rel.gpu.u32 %0, [%1], %2;"
                     : "=r"(ticket) : "l"(&g_arrive), "r"(1u) : "memory");
        if (ticket == (unsigned)gridDim.x - 1u) {
            float tv; unsigned cv;
            asm volatile("ld.acquire.gpu.f32 %0, [%1];"
                         : "=f"(tv) : "l"(&g_total) : "memory");
            asm volatile("ld.acquire.gpu.u32 %0, [%1];"
                         : "=r"(cv) : "l"(&g_count) : "memory");
            out[0] = (cv > 0u) ? (tv / (float)cv) : 0.0f;
            g_total = 0.0f; g_count = 0u; g_arrive = 0u;
        }
    }
}

extern "C" void kernel_launch(void* const* d_in, const int* in_sizes, int n_in,
                              void* d_out, int out_size)
{
    const float* scores      = (const float*)d_in[0];
    const int*   pos_indices = (const int*)  d_in[1];
    const int*   neg_indices = (const int*)  d_in[2];
    const int*   pos_counts  = (const int*)  d_in[3];
    const int*   neg_counts  = (const int*)  d_in[4];
    float*       out         = (float*)d_out;

    const int B = in_sizes[3];
    const int C = in_sizes[0] / B;
    const int P = in_sizes[1] / B;
    const int N = in_sizes[2] / B;

    if (C == 64 && P == 16 && N == 48 && (B % 4) == 0) {
        const int nQuads = B / 4;
        const int blocks = (nQuads + FWARPS - 1) / FWARPS;   // 2048 @ B=32768
        mpcl_fast_kernel<<<blocks, FTHREADS>>>(
            scores, pos_indices, neg_indices, pos_counts, neg_counts, out,
            nQuads);
    } else {
        const int nPairs = (B + 1) / 2;
        int blocks = (nPairs + GWARPS * 2 - 1) / (GWARPS * 2);
        if (blocks > 592) blocks = 592;
        if (blocks < 1)   blocks = 1;
        mpcl_generic_kernel<<<blocks, GTHREADS>>>(
            scores, pos_indices, neg_indices, pos_counts, neg_counts, out,
            B, C, P, N, nPairs);
    }
}